// round 1
// baseline (speedup 1.0000x reference)
#include <cuda_runtime.h>
#include <math.h>

// ---------------- problem constants ----------------
// images: 400 total (100 support, 300 query), 3x84x84
// backbone: 3->64 (84->42) ->64 (42->21) ->128 (21->10) ->512 (10->5)
// outputs: predict_test (300x64) then cls_scores (300x5x5x5)

static const int N_IMG   = 400;
static const int N_SUP   = 100;   // images from xtrain
static const int N_QRY   = 300;

// ---------------- scratch (static device globals; no allocation) ----------------
__device__ float g_f1[400u * 64u * 42u * 42u];    // ~180 MB
__device__ float g_f2[400u * 64u * 21u * 21u];    // ~45 MB
__device__ float g_f3[400u * 128u * 10u * 10u];   // ~20 MB
__device__ float g_f4[400u * 512u * 5u * 5u];     // ~20 MB
__device__ float g_fa[4u * 5u * 512u];            // normalized class prototypes (GAP)

// ---------------- fused conv3x3(SAME) + bias + relu + maxpool2x2 ----------------
// Thread layout: tid = cog * SPAD + s ; s indexes a pooled-output position in a
// TY x TX tile (s < TY*TX active). Each thread accumulates COPT output channels
// times 4 pre-pool conv pixels. Weights repacked in smem as [ci][k][co] so weight
// LDS are warp-uniform broadcasts. Input patch loads are aligned float2.
template<int CIN, int CINC, int COUT, int COCTA, int COPT,
         int HIN, int WIN, int HPO, int WPO, int TY, int TX, int SPAD>
__global__ void __launch_bounds__(SPAD*(COCTA/COPT))
conv_pool_kernel(const float* __restrict__ inA, const float* __restrict__ inB, int nsplit,
                 const float* __restrict__ wgt, const float* __restrict__ bias,
                 float* __restrict__ out)
{
    constexpr int PH = 2*TY + 2;
    constexpr int PW = 2*TX + 2;               // even -> float2 alignment holds
    constexpr int COG = COCTA / COPT;
    constexpr int NT  = SPAD * COG;
    constexpr int TILESX = (WPO + TX - 1) / TX;

    __shared__ __align__(16) float s_in[CINC * PH * PW];
    __shared__ __align__(16) float s_w [CINC * 9 * COCTA];

    const int n     = blockIdx.z;
    const int cob   = blockIdx.y * COCTA;
    const int tileY = blockIdx.x / TILESX;
    const int tileX = blockIdx.x % TILESX;
    const int tid   = threadIdx.x;
    const int s     = tid % SPAD;
    const int cog   = tid / SPAD;
    const bool act  = (s < TY * TX);
    const int yl    = act ? (s / TX) : 0;
    const int xl    = act ? (s % TX) : 0;

    const int oy = 2 * (tileY * TY) - 1;   // input-patch origin (SAME padding)
    const int ox = 2 * (tileX * TX) - 1;

    const float* img = (n < nsplit)
        ? inA + (size_t)n * CIN * HIN * WIN
        : inB + (size_t)(n - nsplit) * CIN * HIN * WIN;

    float acc[COPT][4];
    #pragma unroll
    for (int j = 0; j < COPT; j++) {
        acc[j][0] = acc[j][1] = acc[j][2] = acc[j][3] = 0.f;
    }

    for (int cib = 0; cib < CIN; cib += CINC) {
        __syncthreads();
        // ---- load input patch (zero-padded) ----
        for (int idx = tid; idx < CINC * PH * PW; idx += NT) {
            int ci  = idx / (PH * PW);
            int rem = idx - ci * (PH * PW);
            int r   = rem / PW;
            int cl  = rem - r * PW;
            int gy  = oy + r, gx = ox + cl;
            float v = 0.f;
            if (gy >= 0 && gy < HIN && gx >= 0 && gx < WIN)
                v = img[((size_t)(cib + ci) * HIN + gy) * WIN + gx];
            s_in[idx] = v;
        }
        // ---- load weights, repack [ci][k][co]; coalesced global reads ----
        for (int idx = tid; idx < CINC * 9 * COCTA; idx += NT) {
            int co  = idx / (CINC * 9);
            int rem = idx - co * (CINC * 9);   // = ci*9 + k
            s_w[rem * COCTA + co] =
                wgt[(size_t)(cob + co) * CIN * 9 + (size_t)cib * 9 + rem];
        }
        __syncthreads();

        #pragma unroll 1
        for (int ci = 0; ci < CINC; ci++) {
            // 4x4 register patch (rows 2yl..2yl+3, cols 2xl..2xl+3)
            float p[4][4];
            #pragma unroll
            for (int r = 0; r < 4; r++) {
                const float2* rp = reinterpret_cast<const float2*>(
                    &s_in[ci * PH * PW + (2 * yl + r) * PW + 2 * xl]);
                float2 a = rp[0], b2 = rp[1];
                p[r][0] = a.x;  p[r][1] = a.y;  p[r][2] = b2.x;  p[r][3] = b2.y;
            }
            #pragma unroll
            for (int k = 0; k < 9; k++) {
                const int ky = k / 3, kx = k % 3;
                const float* wp = &s_w[(ci * 9 + k) * COCTA + cog * COPT];
                #pragma unroll
                for (int j = 0; j < COPT; j++) {
                    const float wv = wp[j];
                    acc[j][0] = fmaf(p[ky + 0][kx + 0], wv, acc[j][0]);
                    acc[j][1] = fmaf(p[ky + 0][kx + 1], wv, acc[j][1]);
                    acc[j][2] = fmaf(p[ky + 1][kx + 0], wv, acc[j][2]);
                    acc[j][3] = fmaf(p[ky + 1][kx + 1], wv, acc[j][3]);
                }
            }
        }
    }

    // ---- epilogue: relu(max(conv)+b) == max(relu(conv+b)) since relu monotone ----
    const int gyp = tileY * TY + yl;
    const int gxp = tileX * TX + xl;
    if (act && gyp < HPO && gxp < WPO) {
        #pragma unroll
        for (int j = 0; j < COPT; j++) {
            const int co = cob + cog * COPT + j;
            float m = fmaxf(fmaxf(acc[j][0], acc[j][1]), fmaxf(acc[j][2], acc[j][3]));
            float v = fmaxf(m + bias[co], 0.f);
            out[((size_t)n * COUT + co) * (HPO * WPO) + gyp * WPO + gxp] = v;
        }
    }
}

// ---------------- prototypes: ftr_avg (GAP of class-averaged supports), L2-normalized ----------------
// grid 20 (b*k), block 512 (one thread per channel)
__global__ void proto_kernel(const float* __restrict__ ytr)
{
    const int bk = blockIdx.x;
    const int b = bk / 5, k = bk - b * 5;
    const int c = threadIdx.x;

    float ssum = 0.f, ysum = 0.f;
    for (int n = 0; n < 25; n++) {
        const float y = ytr[(b * 25 + n) * 5 + k];
        ysum += y;
        if (y != 0.f) {
            const float* fp = &g_f4[((size_t)(b * 25 + n) * 512 + c) * 25];
            float sp = 0.f;
            #pragma unroll
            for (int p = 0; p < 25; p++) sp += fp[p];
            ssum = fmaf(y, sp, ssum);
        }
    }
    const float val = ssum / (ysum * 25.f);

    __shared__ float red[512];
    red[c] = val * val;
    __syncthreads();
    for (int o = 256; o > 0; o >>= 1) {
        if (c < o) red[c] += red[c + o];
        __syncthreads();
    }
    const float nrm = fmaxf(sqrtf(red[0]), 1e-12f);
    g_fa[(size_t)bk * 512 + c] = val / nrm;
}

// ---------------- classifier head: predict = l2norm(GAP(fte)) @ wc^T + bc ----------------
// grid 300 (query), block 512
__global__ void predict_kernel(const float* __restrict__ wc, const float* __restrict__ bc,
                               float* __restrict__ out)
{
    const int q = blockIdx.x;
    const int c = threadIdx.x;

    const float* fp = &g_f4[((size_t)(100 + q) * 512 + c) * 25];
    float s = 0.f;
    #pragma unroll
    for (int p = 0; p < 25; p++) s += fp[p];
    s /= 25.f;

    __shared__ float red[512];
    __shared__ float sf[512];
    red[c] = s * s;
    __syncthreads();
    for (int o = 256; o > 0; o >>= 1) {
        if (c < o) red[c] += red[c + o];
        __syncthreads();
    }
    const float nrm = fmaxf(sqrtf(red[0]), 1e-12f);
    sf[c] = s / nrm;
    __syncthreads();

    if (c < 64) {
        float a = bc[c];
        const float* wr = &wc[(size_t)c * 512];
        #pragma unroll 8
        for (int d = 0; d < 512; d++) a = fmaf(sf[d], wr[d], a);
        out[(size_t)q * 64 + c] = a;
    }
}

// ---------------- cosine scores: (300, 5 protos, 25 positions) ----------------
// grid 300 (query), block 256. Channel-chunked staging in smem.
// score[q][i][p] = (sum_c fte[q][c][p] * fa[b][i][c]) / max(||fte[q][:,p]||, eps)
__global__ void score_kernel(float* __restrict__ out)
{
    constexpr int CH = 128;
    __shared__ float sf [CH * 25];
    __shared__ float sfa[5 * 129];   // padded rows to kill bank conflicts
    __shared__ float snrm[25];

    const int q = blockIdx.x;
    const int b = q / 75;
    const int tid = threadIdx.x;
    const float* fbase = &g_f4[(size_t)(100 + q) * 512 * 25];

    float acc = 0.f;                 // dot acc (tid<125) / norm acc (125<=tid<150)
    const int di = tid / 25, dp = tid % 25;   // dot worker (i, p)
    const int pn = tid - 125;                 // norm worker p

    for (int cb = 0; cb < 4; cb++) {
        __syncthreads();
        for (int idx = tid; idx < CH * 25; idx += 256)
            sf[idx] = fbase[cb * CH * 25 + idx];
        for (int idx = tid; idx < 5 * CH; idx += 256) {
            int ii = idx / CH, cc = idx - ii * CH;
            sfa[ii * 129 + cc] = g_fa[((size_t)(b * 5 + ii)) * 512 + cb * CH + cc];
        }
        __syncthreads();
        if (tid < 125) {
            #pragma unroll 4
            for (int c = 0; c < CH; c++)
                acc = fmaf(sf[c * 25 + dp], sfa[di * 129 + c], acc);
        } else if (tid < 150) {
            #pragma unroll 4
            for (int c = 0; c < CH; c++) {
                const float v = sf[c * 25 + pn];
                acc = fmaf(v, v, acc);
            }
        }
    }
    if (tid >= 125 && tid < 150) snrm[pn] = fmaxf(sqrtf(acc), 1e-12f);
    __syncthreads();
    if (tid < 125) out[(size_t)q * 125 + tid] = acc / snrm[dp];
}

// ---------------- launch ----------------
extern "C" void kernel_launch(void* const* d_in, const int* in_sizes, int n_in,
                              void* d_out, int out_size)
{
    const float* xtr = (const float*)d_in[0];
    const float* xte = (const float*)d_in[1];
    const float* ytr = (const float*)d_in[2];
    // d_in[3] = ytest (unused by the reference output)
    const float* w1 = (const float*)d_in[4];  const float* b1 = (const float*)d_in[5];
    const float* w2 = (const float*)d_in[6];  const float* b2 = (const float*)d_in[7];
    const float* w3 = (const float*)d_in[8];  const float* b3 = (const float*)d_in[9];
    const float* w4 = (const float*)d_in[10]; const float* b4 = (const float*)d_in[11];
    const float* wc = (const float*)d_in[12]; const float* bc = (const float*)d_in[13];
    float* out = (float*)d_out;

    float *f1, *f2, *f3, *f4;
    cudaGetSymbolAddress((void**)&f1, g_f1);
    cudaGetSymbolAddress((void**)&f2, g_f2);
    cudaGetSymbolAddress((void**)&f3, g_f3);
    cudaGetSymbolAddress((void**)&f4, g_f4);

    // L1: 3 -> 64, 84x84 -> pooled 42x42 ; tiles 6x6, co tiles 2
    conv_pool_kernel<3, 3, 64, 32, 8, 84, 84, 42, 42, 8, 8, 64>
        <<<dim3(36, 2, (unsigned)N_IMG), 256>>>(xtr, xte, N_SUP, w1, b1, f1);

    // L2: 64 -> 64, 42x42 -> pooled 21x21 ; tiles 3x3, co tiles 2
    conv_pool_kernel<64, 16, 64, 32, 8, 42, 42, 21, 21, 8, 8, 64>
        <<<dim3(9, 2, (unsigned)N_IMG), 256>>>(f1, f1, N_IMG, w2, b2, f2);

    // L3: 64 -> 128, 21x21 -> pooled 10x10 ; tiles 2x2 (5x5 each), co tiles 2
    conv_pool_kernel<64, 16, 128, 64, 8, 21, 21, 10, 10, 5, 5, 32>
        <<<dim3(4, 2, (unsigned)N_IMG), 256>>>(f2, f2, N_IMG, w3, b3, f3);

    // L4: 128 -> 512, 10x10 -> pooled 5x5 ; 1 spatial tile, co tiles 8
    conv_pool_kernel<128, 16, 512, 64, 8, 10, 10, 5, 5, 5, 5, 32>
        <<<dim3(1, 8, (unsigned)N_IMG), 256>>>(f3, f3, N_IMG, w4, b4, f4);

    // Prototypes (class-averaged, GAP'd, L2-normalized)
    proto_kernel<<<20, 512>>>(ytr);

    // Classifier head -> out[0 : 300*64]
    predict_kernel<<<300, 512>>>(wc, bc, out);

    // Cosine scores -> out[19200 : 19200 + 300*125]
    score_kernel<<<300, 256>>>(out + 300 * 64);
}

// round 2
// speedup vs baseline: 1.0033x; 1.0033x over previous
#include <cuda_runtime.h>
#include <math.h>

// ---------------- problem constants ----------------
// images: 400 total (100 support, 300 query), 3x84x84
// backbone: 3->64 (84->42) ->64 (42->21) ->128 (21->10) ->512 (10->5)
// outputs: predict_test (300x64) then cls_scores (300x5x5x5)

static const int N_IMG = 400;
static const int N_SUP = 100;

// ---------------- scratch (static device globals; no allocation) ----------------
__device__ float g_f1[400u * 64u * 42u * 42u];    // ~180 MB
__device__ float g_f2[400u * 64u * 21u * 21u];    // ~45 MB
__device__ float g_f3[400u * 128u * 10u * 10u];   // ~20 MB
__device__ float g_f4[400u * 512u * 5u * 5u];     // ~20 MB
__device__ float g_fa[4u * 5u * 512u];            // normalized class prototypes

// duplicated-weight buffers, layout [ci*9+k][co] with each value stored {w,w}
__device__ float g_w1d[3u   * 9u * 64u  * 2u];
__device__ float g_w2d[64u  * 9u * 64u  * 2u];
__device__ float g_w3d[64u  * 9u * 128u * 2u];
__device__ float g_w4d[128u * 9u * 512u * 2u];

// ---------------- packed f32x2 FMA (Blackwell FFMA2; ptxas never auto-emits) ----
typedef unsigned long long u64_t;
__device__ __forceinline__ float2 fma2(float2 a, float2 b, float2 c) {
    float2 d;
    asm("fma.rn.f32x2 %0, %1, %2, %3;"
        : "=l"(*reinterpret_cast<u64_t*>(&d))
        : "l"(*reinterpret_cast<const u64_t*>(&a)),
          "l"(*reinterpret_cast<const u64_t*>(&b)),
          "l"(*reinterpret_cast<const u64_t*>(&c)));
    return d;
}

// ---------------- weight repack: [co][ci][3][3] -> [ci*9+k][co] duplicated ----
__global__ void repack_kernel(const float* __restrict__ w, float* __restrict__ outdup,
                              int cin, int cout)
{
    const int total = cin * 9 * cout;
    for (int idx = blockIdx.x * blockDim.x + threadIdx.x; idx < total;
         idx += gridDim.x * blockDim.x) {
        const int co  = idx % cout;
        const int rem = idx / cout;           // ci*9 + k
        const float v = w[(size_t)co * cin * 9 + rem];
        outdup[2 * (size_t)idx]     = v;
        outdup[2 * (size_t)idx + 1] = v;
    }
}

// ---------------- fused conv3x3(SAME) + bias + relu + maxpool2x2, f32x2 path ----
// tid = cog*SPAD + s. Each thread: COPT output channels x (2x2 pre-pool pixels),
// horizontal pixel pairs packed into f32x2 accumulators.
// Weights staged as duplicated pairs {w,w}: LDS.128 = 2 packed weights, broadcast.
template<int CIN, int CINC, int COUT, int COCTA, int COPT,
         int HIN, int WIN, int HPO, int WPO, int TY, int TX, int SPAD>
__global__ void __launch_bounds__(SPAD*(COCTA/COPT))
conv_pool_kernel(const float* __restrict__ inA, const float* __restrict__ inB, int nsplit,
                 const float* __restrict__ wdup, const float* __restrict__ bias,
                 float* __restrict__ out)
{
    constexpr int PH  = 2*TY + 2;
    constexpr int PW  = 2*TX + 2;               // even -> float2 alignment holds
    constexpr int COG = COCTA / COPT;
    constexpr int NT  = SPAD * COG;
    constexpr int TILESX = (WPO + TX - 1) / TX;
    constexpr int IN_FLOATS = CINC * PH * PW;
    constexpr int W_ROWS    = CINC * 9;          // rows of duplicated weights per chunk
    constexpr int W_F4_PER_ROW = COCTA / 2;      // float4s per row (COCTA float2s)

    extern __shared__ __align__(16) float smem[];
    float* s_in = smem;                          // IN_FLOATS
    float* s_w  = smem + IN_FLOATS;              // W_ROWS * COCTA * 2 floats

    const int n     = blockIdx.z;
    const int cob   = blockIdx.y * COCTA;
    const int tileY = blockIdx.x / TILESX;
    const int tileX = blockIdx.x % TILESX;
    const int tid   = threadIdx.x;
    const int s     = tid % SPAD;
    const int cog   = tid / SPAD;
    const bool act  = (s < TY * TX);
    const int yl    = act ? (s / TX) : 0;
    const int xl    = act ? (s % TX) : 0;

    const int oy = 2 * (tileY * TY) - 1;         // input-patch origin (SAME padding)
    const int ox = 2 * (tileX * TX) - 1;

    const float* img = (n < nsplit)
        ? inA + (size_t)n * CIN * HIN * WIN
        : inB + (size_t)(n - nsplit) * CIN * HIN * WIN;

    float2 accT[COPT], accB[COPT];               // (row0 c0,c1) / (row1 c0,c1)
    #pragma unroll
    for (int j = 0; j < COPT; j++) {
        accT[j] = make_float2(0.f, 0.f);
        accB[j] = make_float2(0.f, 0.f);
    }

    for (int cib = 0; cib < CIN; cib += CINC) {
        __syncthreads();
        // ---- input patch (zero-padded) ----
        for (int idx = tid; idx < IN_FLOATS; idx += NT) {
            int ci  = idx / (PH * PW);
            int rem = idx - ci * (PH * PW);
            int r   = rem / PW;
            int cl  = rem - r * PW;
            int gy  = oy + r, gx = ox + cl;
            float v = 0.f;
            if (gy >= 0 && gy < HIN && gx >= 0 && gx < WIN)
                v = img[((size_t)(cib + ci) * HIN + gy) * WIN + gx];
            s_in[idx] = v;
        }
        // ---- weights: contiguous duplicated rows, coalesced float4 copies ----
        {
            const float4* src = reinterpret_cast<const float4*>(
                wdup + ((size_t)(cib * 9) * COUT + cob) * 2);
            float4* dst = reinterpret_cast<float4*>(s_w);
            const int srcRowStride = COUT / 2;   // float4s per global row
            for (int idx = tid; idx < W_ROWS * W_F4_PER_ROW; idx += NT) {
                int r  = idx / W_F4_PER_ROW;
                int c4 = idx - r * W_F4_PER_ROW;
                dst[idx] = src[(size_t)r * srcRowStride + c4];
            }
        }
        __syncthreads();

        #pragma unroll 1
        for (int ci = 0; ci < CINC; ci++) {
            // packed patch pairs: 4 rows x {(c0,c1),(c1,c2),(c2,c3)}
            float2 pr[4][3];
            #pragma unroll
            for (int r = 0; r < 4; r++) {
                const float* rowp = &s_in[ci * PH * PW + (2 * yl + r) * PW + 2 * xl];
                float2 a = *reinterpret_cast<const float2*>(rowp);
                float2 b = *reinterpret_cast<const float2*>(rowp + 2);
                pr[r][0] = a;
                pr[r][1] = make_float2(a.y, b.x);
                pr[r][2] = b;
            }
            #pragma unroll
            for (int k = 0; k < 9; k++) {
                const int ky = k / 3, kx = k % 3;
                const float4* wq = reinterpret_cast<const float4*>(
                    &s_w[((ci * 9 + k) * COCTA + cog * COPT) * 2]);
                #pragma unroll
                for (int jj = 0; jj < COPT / 2; jj++) {
                    const float4 w4 = wq[jj];
                    const float2 wlo = make_float2(w4.x, w4.y);
                    const float2 whi = make_float2(w4.z, w4.w);
                    accT[2*jj]   = fma2(pr[ky    ][kx], wlo, accT[2*jj]);
                    accB[2*jj]   = fma2(pr[ky + 1][kx], wlo, accB[2*jj]);
                    accT[2*jj+1] = fma2(pr[ky    ][kx], whi, accT[2*jj+1]);
                    accB[2*jj+1] = fma2(pr[ky + 1][kx], whi, accB[2*jj+1]);
                }
            }
        }
    }

    // relu(max(conv)+b) == max(relu(conv+b)) since relu is monotone
    const int gyp = tileY * TY + yl;
    const int gxp = tileX * TX + xl;
    if (act && gyp < HPO && gxp < WPO) {
        #pragma unroll
        for (int j = 0; j < COPT; j++) {
            const int co = cob + cog * COPT + j;
            float m = fmaxf(fmaxf(accT[j].x, accT[j].y), fmaxf(accB[j].x, accB[j].y));
            float v = fmaxf(m + bias[co], 0.f);
            out[((size_t)n * COUT + co) * (HPO * WPO) + gyp * WPO + gxp] = v;
        }
    }
}

// ---------------- prototypes: GAP of class-averaged supports, L2-normalized ----
__global__ void proto_kernel(const float* __restrict__ ytr)
{
    const int bk = blockIdx.x;
    const int b = bk / 5, k = bk - b * 5;
    const int c = threadIdx.x;

    float ssum = 0.f, ysum = 0.f;
    for (int n = 0; n < 25; n++) {
        const float y = ytr[(b * 25 + n) * 5 + k];
        ysum += y;
        if (y != 0.f) {
            const float* fp = &g_f4[((size_t)(b * 25 + n) * 512 + c) * 25];
            float sp = 0.f;
            #pragma unroll
            for (int p = 0; p < 25; p++) sp += fp[p];
            ssum = fmaf(y, sp, ssum);
        }
    }
    const float val = ssum / (ysum * 25.f);

    __shared__ float red[512];
    red[c] = val * val;
    __syncthreads();
    for (int o = 256; o > 0; o >>= 1) {
        if (c < o) red[c] += red[c + o];
        __syncthreads();
    }
    const float nrm = fmaxf(sqrtf(red[0]), 1e-12f);
    g_fa[(size_t)bk * 512 + c] = val / nrm;
}

// ---------------- classifier head: predict = l2norm(GAP(fte)) @ wc^T + bc ------
__global__ void predict_kernel(const float* __restrict__ wc, const float* __restrict__ bc,
                               float* __restrict__ out)
{
    const int q = blockIdx.x;
    const int c = threadIdx.x;

    const float* fp = &g_f4[((size_t)(100 + q) * 512 + c) * 25];
    float s = 0.f;
    #pragma unroll
    for (int p = 0; p < 25; p++) s += fp[p];
    s /= 25.f;

    __shared__ float red[512];
    __shared__ float sf[512];
    red[c] = s * s;
    __syncthreads();
    for (int o = 256; o > 0; o >>= 1) {
        if (c < o) red[c] += red[c + o];
        __syncthreads();
    }
    const float nrm = fmaxf(sqrtf(red[0]), 1e-12f);
    sf[c] = s / nrm;
    __syncthreads();

    if (c < 64) {
        float a = bc[c];
        const float* wr = &wc[(size_t)c * 512];
        #pragma unroll 8
        for (int d = 0; d < 512; d++) a = fmaf(sf[d], wr[d], a);
        out[(size_t)q * 64 + c] = a;
    }
}

// ---------------- cosine scores: (300, 5 protos, 25 positions) ------------------
__global__ void score_kernel(float* __restrict__ out)
{
    constexpr int CH = 128;
    __shared__ float sf [CH * 25];
    __shared__ float sfa[5 * 129];
    __shared__ float snrm[25];

    const int q = blockIdx.x;
    const int b = q / 75;
    const int tid = threadIdx.x;
    const float* fbase = &g_f4[(size_t)(100 + q) * 512 * 25];

    float acc = 0.f;
    const int di = tid / 25, dp = tid % 25;
    const int pn = tid - 125;

    for (int cb = 0; cb < 4; cb++) {
        __syncthreads();
        for (int idx = tid; idx < CH * 25; idx += 256)
            sf[idx] = fbase[cb * CH * 25 + idx];
        for (int idx = tid; idx < 5 * CH; idx += 256) {
            int ii = idx / CH, cc = idx - ii * CH;
            sfa[ii * 129 + cc] = g_fa[((size_t)(b * 5 + ii)) * 512 + cb * CH + cc];
        }
        __syncthreads();
        if (tid < 125) {
            #pragma unroll 4
            for (int c = 0; c < CH; c++)
                acc = fmaf(sf[c * 25 + dp], sfa[di * 129 + c], acc);
        } else if (tid < 150) {
            #pragma unroll 4
            for (int c = 0; c < CH; c++) {
                const float v = sf[c * 25 + pn];
                acc = fmaf(v, v, acc);
            }
        }
    }
    if (tid >= 125 && tid < 150) snrm[pn] = fmaxf(sqrtf(acc), 1e-12f);
    __syncthreads();
    if (tid < 125) out[(size_t)q * 125 + tid] = acc / snrm[dp];
}

// ---------------- launch ----------------
extern "C" void kernel_launch(void* const* d_in, const int* in_sizes, int n_in,
                              void* d_out, int out_size)
{
    const float* xtr = (const float*)d_in[0];
    const float* xte = (const float*)d_in[1];
    const float* ytr = (const float*)d_in[2];
    const float* w1 = (const float*)d_in[4];  const float* b1 = (const float*)d_in[5];
    const float* w2 = (const float*)d_in[6];  const float* b2 = (const float*)d_in[7];
    const float* w3 = (const float*)d_in[8];  const float* b3 = (const float*)d_in[9];
    const float* w4 = (const float*)d_in[10]; const float* b4 = (const float*)d_in[11];
    const float* wc = (const float*)d_in[12]; const float* bc = (const float*)d_in[13];
    float* out = (float*)d_out;

    float *f1, *f2, *f3, *f4, *w1d, *w2d, *w3d, *w4d;
    cudaGetSymbolAddress((void**)&f1, g_f1);
    cudaGetSymbolAddress((void**)&f2, g_f2);
    cudaGetSymbolAddress((void**)&f3, g_f3);
    cudaGetSymbolAddress((void**)&f4, g_f4);
    cudaGetSymbolAddress((void**)&w1d, g_w1d);
    cudaGetSymbolAddress((void**)&w2d, g_w2d);
    cudaGetSymbolAddress((void**)&w3d, g_w3d);
    cudaGetSymbolAddress((void**)&w4d, g_w4d);

    // weight repack (tiny)
    repack_kernel<<<8,   256>>>(w1, w1d, 3, 64);
    repack_kernel<<<144, 256>>>(w2, w2d, 64, 64);
    repack_kernel<<<288, 256>>>(w3, w3d, 64, 128);
    repack_kernel<<<2304,256>>>(w4, w4d, 128, 512);

    // L1: 3 -> 64, pooled 42x42 exact tiling 6x7 tiles of 7x6
    {
        auto kfn = conv_pool_kernel<3, 3, 64, 64, 8, 84, 84, 42, 42, 7, 6, 42>;
        const int shmem = (3*16*14 + 3*9*64*2) * 4;
        cudaFuncSetAttribute(kfn, cudaFuncAttributeMaxDynamicSharedMemorySize, shmem);
        kfn<<<dim3(42, 1, (unsigned)N_IMG), 336, shmem>>>(xtr, xte, N_SUP, w1d, b1, f1);
    }
    // L2: 64 -> 64, pooled 21x21 exact tiling 3x3 tiles of 7x7
    {
        auto kfn = conv_pool_kernel<64, 16, 64, 64, 8, 42, 42, 21, 21, 7, 7, 49>;
        const int shmem = (16*16*16 + 16*9*64*2) * 4;
        cudaFuncSetAttribute(kfn, cudaFuncAttributeMaxDynamicSharedMemorySize, shmem);
        kfn<<<dim3(9, 1, (unsigned)N_IMG), 392, shmem>>>(f1, f1, N_IMG, w2d, b2, f2);
    }
    // L3: 64 -> 128, pooled 10x10, tiles 2x2 of 5x5 (SPAD 32, 25 active)
    {
        auto kfn = conv_pool_kernel<64, 16, 128, 64, 8, 21, 21, 10, 10, 5, 5, 32>;
        const int shmem = (16*12*12 + 16*9*64*2) * 4;
        cudaFuncSetAttribute(kfn, cudaFuncAttributeMaxDynamicSharedMemorySize, shmem);
        kfn<<<dim3(4, 2, (unsigned)N_IMG), 256, shmem>>>(f2, f2, N_IMG, w3d, b3, f3);
    }
    // L4: 128 -> 512, pooled 5x5, 1 spatial tile (SPAD 32, 25 active), co tiles 8
    {
        auto kfn = conv_pool_kernel<128, 16, 512, 64, 8, 10, 10, 5, 5, 5, 5, 32>;
        const int shmem = (16*12*12 + 16*9*64*2) * 4;
        cudaFuncSetAttribute(kfn, cudaFuncAttributeMaxDynamicSharedMemorySize, shmem);
        kfn<<<dim3(1, 8, (unsigned)N_IMG), 256, shmem>>>(f3, f3, N_IMG, w4d, b4, f4);
    }

    proto_kernel<<<20, 512>>>(ytr);
    predict_kernel<<<300, 512>>>(wc, bc, out);
    score_kernel<<<300, 256>>>(out + 300 * 64);
}